// round 8
// baseline (speedup 1.0000x reference)
#include <cuda_runtime.h>
#include <cuda_fp16.h>

#define NN 50000
#define EE 800000
#define DD 128
#define BN_EPS 1e-5f
#define SCAN_B 1024
#define NBLK ((NN + SCAN_B - 1) / SCAN_B)   // 49

// ---- scratch (device globals: allocation-free per harness rules) ----
__device__ float g_xw[NN * DD];      // x @ W (fp32)
__device__ uint2 g_xwh[NN * DD / 4]; // x @ W (fp16, packed 4/uint2) for gather
__device__ float g_agg[NN * DD];     // aggregated output of GCN conv
__device__ float g_dinv[NN];
__device__ int   g_degi[NN];
__device__ int   g_off[NN + 1];      // CSR offsets
__device__ int   g_cur[NN];          // fill cursors
__device__ int   g_rowi[EE];         // edge rows as int32
__device__ int   g_coli[EE];         // edge cols as int32
__device__ int   g_adj[EE];          // CSR adjacency (col indices)
__device__ int   g_bsum[NBLK];       // per-block scan totals
__device__ float g_colsum[DD];
__device__ float g_colsumsq[DD];
__device__ float g_mean[DD];
__device__ float g_scale[DD];        // gamma * rsqrt(var+eps)
__device__ int   g_is64;             // 1 if edge_index is int64, 0 if int32

// ---- K1: zero degrees + BN accums; block 0 also detects edge dtype ----
__global__ void k_init(const void* __restrict__ ei, int N) {
    __shared__ int s_bad;
    int tid = threadIdx.x;
    if (blockIdx.x == 0) {
        if (tid == 0) s_bad = 0;
        __syncthreads();
        long long v = ((const long long*)ei)[tid];
        if (v < 0 || v >= N) atomicOr(&s_bad, 1);
        __syncthreads();
        if (tid == 0) g_is64 = s_bad ? 0 : 1;
    }
    int i = blockIdx.x * blockDim.x + tid;
    if (i < N) g_degi[i] = 0;
    if (i < DD) { g_colsum[i] = 0.0f; g_colsumsq[i] = 0.0f; }
}

// ---- K2: convert edges to int32 + histogram rows ----
__global__ void k_prep(const void* __restrict__ ei, int E, int N) {
    int e = blockIdx.x * blockDim.x + threadIdx.x;
    if (e >= E) return;
    int row, col;
    if (g_is64) {
        row = (int)((const long long*)ei)[e];
        col = (int)((const long long*)ei)[E + e];
    } else {
        row = ((const int*)ei)[e];
        col = ((const int*)ei)[E + e];
    }
    if ((unsigned)row >= (unsigned)N || (unsigned)col >= (unsigned)N) {
        g_rowi[e] = -1; g_coli[e] = 0;
        return;
    }
    g_rowi[e] = row;
    g_coli[e] = col;
    atomicAdd(&g_degi[row], 1);
}

// ---- K3: per-block inclusive scan + block totals ----
__global__ __launch_bounds__(SCAN_B) void k_scan1(int N) {
    __shared__ int warp_tot[32];
    int tid = threadIdx.x;
    int lane = tid & 31, wid = tid >> 5;
    int i = blockIdx.x * SCAN_B + tid;
    int v = (i < N) ? g_degi[i] : 0;
    int s = v;
#pragma unroll
    for (int d = 1; d < 32; d <<= 1) {
        int t = __shfl_up_sync(0xffffffffu, s, d);
        if (lane >= d) s += t;
    }
    if (lane == 31) warp_tot[wid] = s;
    __syncthreads();
    if (wid == 0) {
        int t = warp_tot[lane];
        int ws = t;
#pragma unroll
        for (int d = 1; d < 32; d <<= 1) {
            int u = __shfl_up_sync(0xffffffffu, ws, d);
            if (lane >= d) ws += u;
        }
        warp_tot[lane] = ws - t;  // exclusive warp offsets
    }
    __syncthreads();
    int incl = s + warp_tot[wid];
    if (i < N) g_off[i + 1] = incl;
    if (tid == SCAN_B - 1) g_bsum[blockIdx.x] = incl;
}

// ---- K4: finalize offsets (add block prefix) + dinv + fill cursors ----
__global__ void k_post(int N) {
    int i = blockIdx.x * blockDim.x + threadIdx.x;
    if (i >= N) return;
    int chunk = i >> 10;
    int boff = 0;
    for (int b = 0; b < chunk; b++) boff += g_bsum[b];
    int incl = g_off[i + 1] + boff;
    g_off[i + 1] = incl;
    int deg = g_degi[i];
    g_cur[i] = incl - deg;
    g_dinv[i] = rsqrtf((float)(deg + 1));
    if (i == 0) g_off[0] = 0;
}

// ---- K5: CSR fill ----
__global__ void k_fill(int E) {
    int e = blockIdx.x * blockDim.x + threadIdx.x;
    if (e >= E) return;
    int row = g_rowi[e];
    if (row < 0) return;
    int pos = atomicAdd(&g_cur[row], 1);
    g_adj[pos] = g_coli[e];
}

// ---- K6: xw = x @ W; epilogue stores fp32 + packed fp16 copies ----
__global__ __launch_bounds__(256) void k_gemm(const float* __restrict__ x,
                                              const float* __restrict__ W,
                                              int N) {
    int lane = threadIdx.x & 31;
    int gw = (blockIdx.x * blockDim.x + threadIdx.x) >> 5;
    int r0 = gw * 8;
    if (r0 >= N) return;
    int rows = min(8, N - r0);

    const float4* W4 = (const float4*)W;
    const float4* x4 = (const float4*)x;

    float4 acc[8];
#pragma unroll
    for (int r = 0; r < 8; r++) acc[r] = make_float4(0.f, 0.f, 0.f, 0.f);

#pragma unroll 4
    for (int k4 = 0; k4 < 32; k4++) {
        float4 wv0 = W4[(k4 * 4 + 0) * 32 + lane];
        float4 wv1 = W4[(k4 * 4 + 1) * 32 + lane];
        float4 wv2 = W4[(k4 * 4 + 2) * 32 + lane];
        float4 wv3 = W4[(k4 * 4 + 3) * 32 + lane];
#pragma unroll
        for (int r = 0; r < 8; r++) {
            int row = r0 + r; if (row >= N) row = N - 1;
            float4 xv = x4[row * 32 + k4];
            acc[r].x = fmaf(xv.x, wv0.x, acc[r].x);
            acc[r].y = fmaf(xv.x, wv0.y, acc[r].y);
            acc[r].z = fmaf(xv.x, wv0.z, acc[r].z);
            acc[r].w = fmaf(xv.x, wv0.w, acc[r].w);
            acc[r].x = fmaf(xv.y, wv1.x, acc[r].x);
            acc[r].y = fmaf(xv.y, wv1.y, acc[r].y);
            acc[r].z = fmaf(xv.y, wv1.z, acc[r].z);
            acc[r].w = fmaf(xv.y, wv1.w, acc[r].w);
            acc[r].x = fmaf(xv.z, wv2.x, acc[r].x);
            acc[r].y = fmaf(xv.z, wv2.y, acc[r].y);
            acc[r].z = fmaf(xv.z, wv2.z, acc[r].z);
            acc[r].w = fmaf(xv.z, wv2.w, acc[r].w);
            acc[r].x = fmaf(xv.w, wv3.x, acc[r].x);
            acc[r].y = fmaf(xv.w, wv3.y, acc[r].y);
            acc[r].z = fmaf(xv.w, wv3.z, acc[r].z);
            acc[r].w = fmaf(xv.w, wv3.w, acc[r].w);
        }
    }

    float4* xw4 = (float4*)g_xw;
#pragma unroll
    for (int r = 0; r < 8; r++) {
        if (r < rows) {
            int row = r0 + r;
            xw4[row * 32 + lane] = acc[r];
            __half2 h0 = __float22half2_rn(make_float2(acc[r].x, acc[r].y));
            __half2 h1 = __float22half2_rn(make_float2(acc[r].z, acc[r].w));
            uint2 u;
            u.x = *(unsigned*)&h0;
            u.y = *(unsigned*)&h1;
            g_xwh[row * 32 + lane] = u;
        }
    }
}

// ---- K7: per-node gather from fp16 table (pure, no atomics/barriers) ----
// agg[n] = dinv[n] * ( xw[n]*dinv[n] + sum_{c in adj(n)} dinv[c]*xwh[c] )
__global__ __launch_bounds__(256) void k_gather(int N) {
    int lane = threadIdx.x & 31;
    int n = (blockIdx.x * blockDim.x + threadIdx.x) >> 5;
    if (n >= N) return;
    int j = g_off[n], end = g_off[n + 1];

    float4 acc = make_float4(0.f, 0.f, 0.f, 0.f);
    for (; j + 2 <= end; j += 2) {            // unroll-2 for MLP
        int c0 = g_adj[j], c1 = g_adj[j + 1];
        float w0 = g_dinv[c0], w1 = g_dinv[c1];
        uint2 u0 = g_xwh[c0 * 32 + lane];
        uint2 u1 = g_xwh[c1 * 32 + lane];
        float2 a0 = __half22float2(*(__half2*)&u0.x);
        float2 b0 = __half22float2(*(__half2*)&u0.y);
        float2 a1 = __half22float2(*(__half2*)&u1.x);
        float2 b1 = __half22float2(*(__half2*)&u1.y);
        acc.x = fmaf(a0.x, w0, fmaf(a1.x, w1, acc.x));
        acc.y = fmaf(a0.y, w0, fmaf(a1.y, w1, acc.y));
        acc.z = fmaf(b0.x, w0, fmaf(b1.x, w1, acc.z));
        acc.w = fmaf(b0.y, w0, fmaf(b1.y, w1, acc.w));
    }
    if (j < end) {
        int c0 = g_adj[j];
        float w0 = g_dinv[c0];
        uint2 u0 = g_xwh[c0 * 32 + lane];
        float2 a0 = __half22float2(*(__half2*)&u0.x);
        float2 b0 = __half22float2(*(__half2*)&u0.y);
        acc.x = fmaf(a0.x, w0, acc.x);
        acc.y = fmaf(a0.y, w0, acc.y);
        acc.z = fmaf(b0.x, w0, acc.z);
        acc.w = fmaf(b0.y, w0, acc.w);
    }
    float dr = g_dinv[n];
    float4 sv = ((const float4*)g_xw)[n * 32 + lane];   // self term fp32
    acc.x = (acc.x + sv.x * dr) * dr;
    acc.y = (acc.y + sv.y * dr) * dr;
    acc.z = (acc.z + sv.z * dr) * dr;
    acc.w = (acc.w + sv.w * dr) * dr;
    ((float4*)g_agg)[n * 32 + lane] = acc;
}

// ---- K8: BN column statistics (512 blocks: spread REDs, proven cheap) ----
__global__ void k_bnstats(int N) {
    int c = threadIdx.x;
    float s = 0.f, s2 = 0.f;
    for (int r = blockIdx.x; r < N; r += gridDim.x) {
        float v = g_agg[r * DD + c];
        s += v;
        s2 = fmaf(v, v, s2);
    }
    atomicAdd(&g_colsum[c], s);
    atomicAdd(&g_colsumsq[c], s2);
}

// ---- K9: finalize BN params (bias b cancels through mean subtraction) ----
__global__ void k_bnparam(const float* __restrict__ gamma, float nInv) {
    int c = threadIdx.x;
    float mean = g_colsum[c] * nInv;
    float var = g_colsumsq[c] * nInv - mean * mean;
    g_mean[c] = mean;
    g_scale[c] = rsqrtf(var + BN_EPS) * gamma[c];
}

// ---- K10: y = relu((agg - mean)*scale + beta) + x ----
__global__ void k_final(const float* __restrict__ x, const float* __restrict__ beta,
                        float* __restrict__ out, int n4) {
    int t = blockIdx.x * blockDim.x + threadIdx.x;
    if (t >= n4) return;
    int cb = t & 31;
    float4 a  = ((const float4*)g_agg)[t];
    float4 xr = ((const float4*)x)[t];
    float4 m  = ((const float4*)g_mean)[cb];
    float4 s  = ((const float4*)g_scale)[cb];
    float4 bt = ((const float4*)beta)[cb];
    float4 r;
    r.x = fmaxf((a.x - m.x) * s.x + bt.x, 0.f) + xr.x;
    r.y = fmaxf((a.y - m.y) * s.y + bt.y, 0.f) + xr.y;
    r.z = fmaxf((a.z - m.z) * s.z + bt.z, 0.f) + xr.z;
    r.w = fmaxf((a.w - m.w) * s.w + bt.w, 0.f) + xr.w;
    ((float4*)out)[t] = r;
}

extern "C" void kernel_launch(void* const* d_in, const int* in_sizes, int n_in,
                              void* d_out, int out_size) {
    const float* x     = (const float*)d_in[0];
    const void*  ei    = d_in[1];
    const float* W     = (const float*)d_in[2];
    // d_in[3] = b — cancels exactly through BatchNorm, unused
    const float* gamma = (const float*)d_in[4];
    const float* beta  = (const float*)d_in[5];
    float*       out   = (float*)d_out;

    int N = in_sizes[0] / DD;
    int E = in_sizes[1] / 2;
    int nblk = (N + SCAN_B - 1) / SCAN_B;

    static cudaStream_t s2 = nullptr;
    static cudaEvent_t ev_fork = nullptr, ev_join = nullptr;
    if (s2 == nullptr) {
        cudaStreamCreateWithFlags(&s2, cudaStreamNonBlocking);
        cudaEventCreateWithFlags(&ev_fork, cudaEventDisableTiming);
        cudaEventCreateWithFlags(&ev_join, cudaEventDisableTiming);
    }

    // ---- fork: GEMM (x,W only) runs concurrently with the CSR build ----
    cudaEventRecord(ev_fork, 0);
    cudaStreamWaitEvent(s2, ev_fork, 0);
    int gwarps = (N + 7) / 8;
    k_gemm<<<(gwarps + 7) / 8, 256, 0, s2>>>(x, W, N);
    cudaEventRecord(ev_join, s2);

    // ---- CSR build chain on the main stream ----
    k_init<<<(N + 255) / 256, 256>>>(ei, N);
    k_prep<<<(E + 255) / 256, 256>>>(ei, E, N);
    k_scan1<<<nblk, SCAN_B>>>(N);
    k_post<<<(N + 255) / 256, 256>>>(N);
    k_fill<<<(E + 255) / 256, 256>>>(E);

    // ---- join, then aggregate ----
    cudaStreamWaitEvent(0, ev_join, 0);
    k_gather<<<(N + 7) / 8, 256>>>(N);

    k_bnstats<<<512, 128>>>(N);
    k_bnparam<<<1, DD>>>(gamma, 1.0f / (float)N);

    int n4 = N * (DD / 4);
    k_final<<<(n4 + 255) / 256, 256>>>(x, beta, out, n4);
}

// round 9
// speedup vs baseline: 1.0809x; 1.0809x over previous
#include <cuda_runtime.h>
#include <cuda_fp16.h>

#define NN 50000
#define EE 800000
#define DD 128
#define BN_EPS 1e-5f
#define SCAN_B 1024
#define NBLK ((NN + SCAN_B - 1) / SCAN_B)   // 49

// ---- scratch (device globals: allocation-free per harness rules) ----
__device__ float    g_xw[NN * DD];            // x @ W (fp32)
__device__ __align__(16) unsigned g_xwh32[NN * 64];  // x @ W as half2 pairs (gather table)
__device__ unsigned g_wt[DD * DD];            // W pre-converted to tf32 bits
__device__ float    g_agg[NN * DD];
__device__ float    g_dinv[NN];
__device__ int      g_degi[NN];
__device__ int      g_off[NN + 1];
__device__ int      g_cur[NN];
__device__ int      g_rowi[EE];
__device__ int      g_coli[EE];
__device__ int      g_adj[EE];
__device__ int      g_bsum[NBLK];
__device__ float    g_colsum[DD];
__device__ float    g_colsumsq[DD];
__device__ float    g_mean[DD];
__device__ float    g_scale[DD];
__device__ int      g_is64;

// ---- K1: zero degrees + BN accums; block 0 also detects edge dtype ----
__global__ void k_init(const void* __restrict__ ei, int N) {
    __shared__ int s_bad;
    int tid = threadIdx.x;
    if (blockIdx.x == 0) {
        if (tid == 0) s_bad = 0;
        __syncthreads();
        long long v = ((const long long*)ei)[tid];
        if (v < 0 || v >= N) atomicOr(&s_bad, 1);
        __syncthreads();
        if (tid == 0) g_is64 = s_bad ? 0 : 1;
    }
    int i = blockIdx.x * blockDim.x + tid;
    if (i < N) g_degi[i] = 0;
    if (i < DD) { g_colsum[i] = 0.0f; g_colsumsq[i] = 0.0f; }
}

// ---- K2: convert edges to int32 + histogram rows ----
__global__ void k_prep(const void* __restrict__ ei, int E, int N) {
    int e = blockIdx.x * blockDim.x + threadIdx.x;
    if (e >= E) return;
    int row, col;
    if (g_is64) {
        row = (int)((const long long*)ei)[e];
        col = (int)((const long long*)ei)[E + e];
    } else {
        row = ((const int*)ei)[e];
        col = ((const int*)ei)[E + e];
    }
    if ((unsigned)row >= (unsigned)N || (unsigned)col >= (unsigned)N) {
        g_rowi[e] = -1; g_coli[e] = 0;
        return;
    }
    g_rowi[e] = row;
    g_coli[e] = col;
    atomicAdd(&g_degi[row], 1);
}

// ---- K3: per-block inclusive scan + block totals ----
__global__ __launch_bounds__(SCAN_B) void k_scan1(int N) {
    __shared__ int warp_tot[32];
    int tid = threadIdx.x;
    int lane = tid & 31, wid = tid >> 5;
    int i = blockIdx.x * SCAN_B + tid;
    int v = (i < N) ? g_degi[i] : 0;
    int s = v;
#pragma unroll
    for (int d = 1; d < 32; d <<= 1) {
        int t = __shfl_up_sync(0xffffffffu, s, d);
        if (lane >= d) s += t;
    }
    if (lane == 31) warp_tot[wid] = s;
    __syncthreads();
    if (wid == 0) {
        int t = warp_tot[lane];
        int ws = t;
#pragma unroll
        for (int d = 1; d < 32; d <<= 1) {
            int u = __shfl_up_sync(0xffffffffu, ws, d);
            if (lane >= d) ws += u;
        }
        warp_tot[lane] = ws - t;
    }
    __syncthreads();
    int incl = s + warp_tot[wid];
    if (i < N) g_off[i + 1] = incl;
    if (tid == SCAN_B - 1) g_bsum[blockIdx.x] = incl;
}

// ---- K4: finalize offsets + dinv + fill cursors ----
__global__ void k_post(int N) {
    int i = blockIdx.x * blockDim.x + threadIdx.x;
    if (i >= N) return;
    int chunk = i >> 10;
    int boff = 0;
    for (int b = 0; b < chunk; b++) boff += g_bsum[b];
    int incl = g_off[i + 1] + boff;
    g_off[i + 1] = incl;
    int deg = g_degi[i];
    g_cur[i] = incl - deg;
    g_dinv[i] = rsqrtf((float)(deg + 1));
    if (i == 0) g_off[0] = 0;
}

// ---- K5: CSR fill ----
__global__ void k_fill(int E) {
    int e = blockIdx.x * blockDim.x + threadIdx.x;
    if (e >= E) return;
    int row = g_rowi[e];
    if (row < 0) return;
    int pos = atomicAdd(&g_cur[row], 1);
    g_adj[pos] = g_coli[e];
}

// ---- K6a: pre-convert W to tf32 bit pattern ----
__global__ void k_wcvt(const float* __restrict__ W) {
    int i = blockIdx.x * blockDim.x + threadIdx.x;
    if (i < DD * DD) {
        unsigned u;
        asm("cvt.rna.tf32.f32 %0, %1;" : "=r"(u) : "f"(W[i]));
        g_wt[i] = u;
    }
}

// ---- K6b: xw = x @ W via TF32 mma.sync (warp = 16 rows x 128 cols) ----
__global__ __launch_bounds__(256) void k_gemm_tc(const float* __restrict__ x, int N) {
    int lane = threadIdx.x & 31;
    int warp = (blockIdx.x * blockDim.x + threadIdx.x) >> 5;
    int r0 = warp * 16;
    if (r0 >= N) return;
    int gid = lane >> 2;      // 0..7
    int tig = lane & 3;       // 0..3

    float c[16][4];
#pragma unroll
    for (int nt = 0; nt < 16; nt++)
        c[nt][0] = c[nt][1] = c[nt][2] = c[nt][3] = 0.f;

    const float* xr0 = x + (r0 + gid) * DD;        // rows r0+gid
    const float* xr1 = xr0 + 8 * DD;               // rows r0+8+gid

#pragma unroll
    for (int kt = 0; kt < 16; kt++) {
        int k0 = kt * 8;
        unsigned A0, A1, A2, A3;
        {
            float a0 = xr0[k0 + tig];
            float a1 = xr1[k0 + tig];
            float a2 = xr0[k0 + tig + 4];
            float a3 = xr1[k0 + tig + 4];
            asm("cvt.rna.tf32.f32 %0, %1;" : "=r"(A0) : "f"(a0));
            asm("cvt.rna.tf32.f32 %0, %1;" : "=r"(A1) : "f"(a1));
            asm("cvt.rna.tf32.f32 %0, %1;" : "=r"(A2) : "f"(a2));
            asm("cvt.rna.tf32.f32 %0, %1;" : "=r"(A3) : "f"(a3));
        }
#pragma unroll
        for (int nt = 0; nt < 16; nt++) {
            unsigned B0 = g_wt[(k0 + tig) * DD + nt * 8 + gid];
            unsigned B1 = g_wt[(k0 + tig + 4) * DD + nt * 8 + gid];
            asm volatile(
                "mma.sync.aligned.m16n8k8.row.col.f32.tf32.tf32.f32 "
                "{%0,%1,%2,%3}, {%4,%5,%6,%7}, {%8,%9}, {%0,%1,%2,%3};"
                : "+f"(c[nt][0]), "+f"(c[nt][1]), "+f"(c[nt][2]), "+f"(c[nt][3])
                : "r"(A0), "r"(A1), "r"(A2), "r"(A3), "r"(B0), "r"(B1));
        }
    }

    int row0 = r0 + gid, row1 = r0 + 8 + gid;
#pragma unroll
    for (int nt = 0; nt < 16; nt++) {
        int col = nt * 8 + 2 * tig;          // even
        ((float2*)g_xw)[(row0 * DD + col) >> 1] = make_float2(c[nt][0], c[nt][1]);
        ((float2*)g_xw)[(row1 * DD + col) >> 1] = make_float2(c[nt][2], c[nt][3]);
        __half2 h0 = __float22half2_rn(make_float2(c[nt][0], c[nt][1]));
        __half2 h1 = __float22half2_rn(make_float2(c[nt][2], c[nt][3]));
        g_xwh32[row0 * 64 + (col >> 1)] = *(unsigned*)&h0;
        g_xwh32[row1 * 64 + (col >> 1)] = *(unsigned*)&h1;
    }
}

// ---- K7: per-node gather from fp16 table (pure, no atomics/barriers) ----
__global__ __launch_bounds__(256) void k_gather(int N) {
    int lane = threadIdx.x & 31;
    int n = (blockIdx.x * blockDim.x + threadIdx.x) >> 5;
    if (n >= N) return;
    int j = g_off[n], end = g_off[n + 1];
    const uint2* xwh = (const uint2*)g_xwh32;

    float4 acc = make_float4(0.f, 0.f, 0.f, 0.f);
    for (; j + 2 <= end; j += 2) {
        int c0 = g_adj[j], c1 = g_adj[j + 1];
        float w0 = g_dinv[c0], w1 = g_dinv[c1];
        uint2 u0 = xwh[c0 * 32 + lane];
        uint2 u1 = xwh[c1 * 32 + lane];
        float2 a0 = __half22float2(*(__half2*)&u0.x);
        float2 b0 = __half22float2(*(__half2*)&u0.y);
        float2 a1 = __half22float2(*(__half2*)&u1.x);
        float2 b1 = __half22float2(*(__half2*)&u1.y);
        acc.x = fmaf(a0.x, w0, fmaf(a1.x, w1, acc.x));
        acc.y = fmaf(a0.y, w0, fmaf(a1.y, w1, acc.y));
        acc.z = fmaf(b0.x, w0, fmaf(b1.x, w1, acc.z));
        acc.w = fmaf(b0.y, w0, fmaf(b1.y, w1, acc.w));
    }
    if (j < end) {
        int c0 = g_adj[j];
        float w0 = g_dinv[c0];
        uint2 u0 = xwh[c0 * 32 + lane];
        float2 a0 = __half22float2(*(__half2*)&u0.x);
        float2 b0 = __half22float2(*(__half2*)&u0.y);
        acc.x = fmaf(a0.x, w0, acc.x);
        acc.y = fmaf(a0.y, w0, acc.y);
        acc.z = fmaf(b0.x, w0, acc.z);
        acc.w = fmaf(b0.y, w0, acc.w);
    }
    float dr = g_dinv[n];
    float4 sv = ((const float4*)g_xw)[n * 32 + lane];   // self term fp32
    acc.x = (acc.x + sv.x * dr) * dr;
    acc.y = (acc.y + sv.y * dr) * dr;
    acc.z = (acc.z + sv.z * dr) * dr;
    acc.w = (acc.w + sv.w * dr) * dr;
    ((float4*)g_agg)[n * 32 + lane] = acc;
}

// ---- K8: BN column statistics ----
__global__ void k_bnstats(int N) {
    int c = threadIdx.x;
    float s = 0.f, s2 = 0.f;
    for (int r = blockIdx.x; r < N; r += gridDim.x) {
        float v = g_agg[r * DD + c];
        s += v;
        s2 = fmaf(v, v, s2);
    }
    atomicAdd(&g_colsum[c], s);
    atomicAdd(&g_colsumsq[c], s2);
}

// ---- K9: finalize BN params (bias b cancels through mean subtraction) ----
__global__ void k_bnparam(const float* __restrict__ gamma, float nInv) {
    int c = threadIdx.x;
    float mean = g_colsum[c] * nInv;
    float var = g_colsumsq[c] * nInv - mean * mean;
    g_mean[c] = mean;
    g_scale[c] = rsqrtf(var + BN_EPS) * gamma[c];
}

// ---- K10: y = relu((agg - mean)*scale + beta) + x ----
__global__ void k_final(const float* __restrict__ x, const float* __restrict__ beta,
                        float* __restrict__ out, int n4) {
    int t = blockIdx.x * blockDim.x + threadIdx.x;
    if (t >= n4) return;
    int cb = t & 31;
    float4 a  = ((const float4*)g_agg)[t];
    float4 xr = ((const float4*)x)[t];
    float4 m  = ((const float4*)g_mean)[cb];
    float4 s  = ((const float4*)g_scale)[cb];
    float4 bt = ((const float4*)beta)[cb];
    float4 r;
    r.x = fmaxf((a.x - m.x) * s.x + bt.x, 0.f) + xr.x;
    r.y = fmaxf((a.y - m.y) * s.y + bt.y, 0.f) + xr.y;
    r.z = fmaxf((a.z - m.z) * s.z + bt.z, 0.f) + xr.z;
    r.w = fmaxf((a.w - m.w) * s.w + bt.w, 0.f) + xr.w;
    ((float4*)out)[t] = r;
}

extern "C" void kernel_launch(void* const* d_in, const int* in_sizes, int n_in,
                              void* d_out, int out_size) {
    const float* x     = (const float*)d_in[0];
    const void*  ei    = d_in[1];
    const float* W     = (const float*)d_in[2];
    // d_in[3] = b — cancels exactly through BatchNorm, unused
    const float* gamma = (const float*)d_in[4];
    const float* beta  = (const float*)d_in[5];
    float*       out   = (float*)d_out;

    int N = in_sizes[0] / DD;
    int E = in_sizes[1] / 2;
    int nblk = (N + SCAN_B - 1) / SCAN_B;

    static cudaStream_t s2 = nullptr;
    static cudaEvent_t ev_fork = nullptr, ev_join = nullptr;
    if (s2 == nullptr) {
        cudaStreamCreateWithFlags(&s2, cudaStreamNonBlocking);
        cudaEventCreateWithFlags(&ev_fork, cudaEventDisableTiming);
        cudaEventCreateWithFlags(&ev_join, cudaEventDisableTiming);
    }

    // ---- fork: W-convert + TC GEMM run concurrently with the CSR build ----
    cudaEventRecord(ev_fork, 0);
    cudaStreamWaitEvent(s2, ev_fork, 0);
    k_wcvt<<<(DD * DD + 255) / 256, 256, 0, s2>>>(W);
    int gwarps = (N + 15) / 16;                 // 3125 warps
    k_gemm_tc<<<(gwarps + 7) / 8, 256, 0, s2>>>(x, N);
    cudaEventRecord(ev_join, s2);

    // ---- CSR build chain on the main stream ----
    k_init<<<(N + 255) / 256, 256>>>(ei, N);
    k_prep<<<(E + 255) / 256, 256>>>(ei, E, N);
    k_scan1<<<nblk, SCAN_B>>>(N);
    k_post<<<(N + 255) / 256, 256>>>(N);
    k_fill<<<(E + 255) / 256, 256>>>(E);

    // ---- join, then aggregate ----
    cudaStreamWaitEvent(0, ev_join, 0);
    k_gather<<<(N + 7) / 8, 256>>>(N);

    k_bnstats<<<512, 128>>>(N);
    k_bnparam<<<1, DD>>>(gamma, 1.0f / (float)N);

    int n4 = N * (DD / 4);
    k_final<<<(n4 + 255) / 256, 256>>>(x, beta, out, n4);
}

// round 10
// speedup vs baseline: 1.5773x; 1.4592x over previous
#include <cuda_runtime.h>
#include <cuda_fp16.h>

#define NN 50000
#define EE 800000
#define DD 128
#define BN_EPS 1e-5f
#define SCAN_B 1024
#define NBLK ((NN + SCAN_B - 1) / SCAN_B)   // 49

// ---- scratch (device globals: allocation-free per harness rules) ----
__device__ __align__(16) unsigned g_xwh32[NN * 64];  // x@W as half2 pairs (only copy)
__device__ unsigned g_wt[DD * DD];            // W pre-converted to tf32 bits
__device__ float    g_agg[NN * DD];
__device__ float    g_dinv[NN];
__device__ int      g_degi[NN];
__device__ int      g_off[NN + 1];
__device__ int      g_cur[NN];
__device__ int      g_adj[EE];
__device__ int      g_bsum[NBLK];
__device__ float    g_colsum[DD];
__device__ float    g_colsumsq[DD];
__device__ int      g_is64;

// ---- K1: zero degrees + BN accums; block 0 also detects edge dtype ----
__global__ void k_init(const void* __restrict__ ei, int N) {
    __shared__ int s_bad;
    int tid = threadIdx.x;
    if (blockIdx.x == 0) {
        if (tid == 0) s_bad = 0;
        __syncthreads();
        long long v = ((const long long*)ei)[tid];
        if (v < 0 || v >= N) atomicOr(&s_bad, 1);
        __syncthreads();
        if (tid == 0) g_is64 = s_bad ? 0 : 1;
    }
    int i = blockIdx.x * blockDim.x + tid;
    if (i < N) g_degi[i] = 0;
    if (i < DD) { g_colsum[i] = 0.0f; g_colsumsq[i] = 0.0f; }
}

// ---- K2: histogram rows (decode only; no intermediate arrays) ----
__global__ void k_prep(const void* __restrict__ ei, int E, int N) {
    int e = blockIdx.x * blockDim.x + threadIdx.x;
    if (e >= E) return;
    int row = g_is64 ? (int)((const long long*)ei)[e] : ((const int*)ei)[e];
    if ((unsigned)row < (unsigned)N) atomicAdd(&g_degi[row], 1);
}

// ---- K3: per-block inclusive scan + block totals ----
__global__ __launch_bounds__(SCAN_B) void k_scan1(int N) {
    __shared__ int warp_tot[32];
    int tid = threadIdx.x;
    int lane = tid & 31, wid = tid >> 5;
    int i = blockIdx.x * SCAN_B + tid;
    int v = (i < N) ? g_degi[i] : 0;
    int s = v;
#pragma unroll
    for (int d = 1; d < 32; d <<= 1) {
        int t = __shfl_up_sync(0xffffffffu, s, d);
        if (lane >= d) s += t;
    }
    if (lane == 31) warp_tot[wid] = s;
    __syncthreads();
    if (wid == 0) {
        int t = warp_tot[lane];
        int ws = t;
#pragma unroll
        for (int d = 1; d < 32; d <<= 1) {
            int u = __shfl_up_sync(0xffffffffu, ws, d);
            if (lane >= d) ws += u;
        }
        warp_tot[lane] = ws - t;
    }
    __syncthreads();
    int incl = s + warp_tot[wid];
    if (i < N) g_off[i + 1] = incl;
    if (tid == SCAN_B - 1) g_bsum[blockIdx.x] = incl;
}

// ---- K4: finalize offsets + dinv + fill cursors ----
__global__ void k_post(int N) {
    int i = blockIdx.x * blockDim.x + threadIdx.x;
    if (i >= N) return;
    int chunk = i >> 10;
    int boff = 0;
    for (int b = 0; b < chunk; b++) boff += g_bsum[b];
    int incl = g_off[i + 1] + boff;
    g_off[i + 1] = incl;
    int deg = g_degi[i];
    g_cur[i] = incl - deg;
    g_dinv[i] = rsqrtf((float)(deg + 1));
    if (i == 0) g_off[0] = 0;
}

// ---- K5: CSR fill (re-decodes ei; L2-resident after prep) ----
__global__ void k_fill(const void* __restrict__ ei, int E, int N) {
    int e = blockIdx.x * blockDim.x + threadIdx.x;
    if (e >= E) return;
    int row, col;
    if (g_is64) {
        row = (int)((const long long*)ei)[e];
        col = (int)((const long long*)ei)[E + e];
    } else {
        row = ((const int*)ei)[e];
        col = ((const int*)ei)[E + e];
    }
    if ((unsigned)row >= (unsigned)N || (unsigned)col >= (unsigned)N) return;
    int pos = atomicAdd(&g_cur[row], 1);
    g_adj[pos] = col;
}

// ---- K6a: pre-convert W to tf32 bit pattern ----
__global__ void k_wcvt(const float* __restrict__ W) {
    int i = blockIdx.x * blockDim.x + threadIdx.x;
    if (i < DD * DD) {
        unsigned u;
        asm("cvt.rna.tf32.f32 %0, %1;" : "=r"(u) : "f"(W[i]));
        g_wt[i] = u;
    }
}

// ---- K6b: xw = x @ W via TF32 mma.sync (warp = 16 rows x 128 cols) ----
// Epilogue stores ONLY the fp16 table.
__global__ __launch_bounds__(256) void k_gemm_tc(const float* __restrict__ x, int N) {
    int lane = threadIdx.x & 31;
    int warp = (blockIdx.x * blockDim.x + threadIdx.x) >> 5;
    int r0 = warp * 16;
    if (r0 >= N) return;
    int gid = lane >> 2;      // 0..7
    int tig = lane & 3;       // 0..3

    float c[16][4];
#pragma unroll
    for (int nt = 0; nt < 16; nt++)
        c[nt][0] = c[nt][1] = c[nt][2] = c[nt][3] = 0.f;

    const float* xr0 = x + (r0 + gid) * DD;
    const float* xr1 = xr0 + 8 * DD;

#pragma unroll
    for (int kt = 0; kt < 16; kt++) {
        int k0 = kt * 8;
        unsigned A0, A1, A2, A3;
        {
            float a0 = xr0[k0 + tig];
            float a1 = xr1[k0 + tig];
            float a2 = xr0[k0 + tig + 4];
            float a3 = xr1[k0 + tig + 4];
            asm("cvt.rna.tf32.f32 %0, %1;" : "=r"(A0) : "f"(a0));
            asm("cvt.rna.tf32.f32 %0, %1;" : "=r"(A1) : "f"(a1));
            asm("cvt.rna.tf32.f32 %0, %1;" : "=r"(A2) : "f"(a2));
            asm("cvt.rna.tf32.f32 %0, %1;" : "=r"(A3) : "f"(a3));
        }
#pragma unroll
        for (int nt = 0; nt < 16; nt++) {
            unsigned B0 = g_wt[(k0 + tig) * DD + nt * 8 + gid];
            unsigned B1 = g_wt[(k0 + tig + 4) * DD + nt * 8 + gid];
            asm volatile(
                "mma.sync.aligned.m16n8k8.row.col.f32.tf32.tf32.f32 "
                "{%0,%1,%2,%3}, {%4,%5,%6,%7}, {%8,%9}, {%0,%1,%2,%3};"
                : "+f"(c[nt][0]), "+f"(c[nt][1]), "+f"(c[nt][2]), "+f"(c[nt][3])
                : "r"(A0), "r"(A1), "r"(A2), "r"(A3), "r"(B0), "r"(B1));
        }
    }

    int row0 = r0 + gid, row1 = r0 + 8 + gid;
#pragma unroll
    for (int nt = 0; nt < 16; nt++) {
        int cH = (nt * 8 + 2 * tig) >> 1;      // half2 column index
        __half2 h0 = __float22half2_rn(make_float2(c[nt][0], c[nt][1]));
        __half2 h1 = __float22half2_rn(make_float2(c[nt][2], c[nt][3]));
        g_xwh32[row0 * 64 + cH] = *(unsigned*)&h0;
        g_xwh32[row1 * 64 + cH] = *(unsigned*)&h1;
    }
}

// ---- K7: per-node gather from fp16 table (pure; unroll-4) ----
__global__ __launch_bounds__(256) void k_gather(int N) {
    int lane = threadIdx.x & 31;
    int n = (blockIdx.x * blockDim.x + threadIdx.x) >> 5;
    if (n >= N) return;
    int j = g_off[n], end = g_off[n + 1];
    const uint2* xwh = (const uint2*)g_xwh32;

    float4 acc = make_float4(0.f, 0.f, 0.f, 0.f);
    for (; j + 4 <= end; j += 4) {
        int c0 = g_adj[j], c1 = g_adj[j + 1], c2 = g_adj[j + 2], c3 = g_adj[j + 3];
        float w0 = g_dinv[c0], w1 = g_dinv[c1], w2 = g_dinv[c2], w3 = g_dinv[c3];
        uint2 u0 = xwh[c0 * 32 + lane];
        uint2 u1 = xwh[c1 * 32 + lane];
        uint2 u2 = xwh[c2 * 32 + lane];
        uint2 u3 = xwh[c3 * 32 + lane];
        float2 a0 = __half22float2(*(__half2*)&u0.x), b0 = __half22float2(*(__half2*)&u0.y);
        float2 a1 = __half22float2(*(__half2*)&u1.x), b1 = __half22float2(*(__half2*)&u1.y);
        float2 a2 = __half22float2(*(__half2*)&u2.x), b2 = __half22float2(*(__half2*)&u2.y);
        float2 a3 = __half22float2(*(__half2*)&u3.x), b3 = __half22float2(*(__half2*)&u3.y);
        acc.x = fmaf(a0.x, w0, fmaf(a1.x, w1, fmaf(a2.x, w2, fmaf(a3.x, w3, acc.x))));
        acc.y = fmaf(a0.y, w0, fmaf(a1.y, w1, fmaf(a2.y, w2, fmaf(a3.y, w3, acc.y))));
        acc.z = fmaf(b0.x, w0, fmaf(b1.x, w1, fmaf(b2.x, w2, fmaf(b3.x, w3, acc.z))));
        acc.w = fmaf(b0.y, w0, fmaf(b1.y, w1, fmaf(b2.y, w2, fmaf(b3.y, w3, acc.w))));
    }
    for (; j < end; j++) {
        int c0 = g_adj[j];
        float w0 = g_dinv[c0];
        uint2 u0 = xwh[c0 * 32 + lane];
        float2 a0 = __half22float2(*(__half2*)&u0.x), b0 = __half22float2(*(__half2*)&u0.y);
        acc.x = fmaf(a0.x, w0, acc.x);
        acc.y = fmaf(a0.y, w0, acc.y);
        acc.z = fmaf(b0.x, w0, acc.z);
        acc.w = fmaf(b0.y, w0, acc.w);
    }
    float dr = g_dinv[n];
    uint2 us = xwh[n * 32 + lane];                 // self term (fp16 table)
    float2 sa = __half22float2(*(__half2*)&us.x), sb = __half22float2(*(__half2*)&us.y);
    acc.x = (acc.x + sa.x * dr) * dr;
    acc.y = (acc.y + sa.y * dr) * dr;
    acc.z = (acc.z + sb.x * dr) * dr;
    acc.w = (acc.w + sb.y * dr) * dr;
    ((float4*)g_agg)[n * 32 + lane] = acc;
}

// ---- K8: BN column statistics ----
__global__ void k_bnstats(int N) {
    int c = threadIdx.x;
    float s = 0.f, s2 = 0.f;
    for (int r = blockIdx.x; r < N; r += gridDim.x) {
        float v = g_agg[r * DD + c];
        s += v;
        s2 = fmaf(v, v, s2);
    }
    atomicAdd(&g_colsum[c], s);
    atomicAdd(&g_colsumsq[c], s2);
}

// ---- K9: y = relu((agg-mean)*scale + beta) + x, BN params computed per-block ----
__global__ __launch_bounds__(256) void k_final(const float* __restrict__ x,
                                               const float* __restrict__ gamma,
                                               const float* __restrict__ beta,
                                               float* __restrict__ out,
                                               int n4, float nInv) {
    __shared__ float s_mean[DD], s_scale[DD];
    int tid = threadIdx.x;
    if (tid < DD) {
        float mean = g_colsum[tid] * nInv;
        float var = g_colsumsq[tid] * nInv - mean * mean;
        s_mean[tid] = mean;
        s_scale[tid] = rsqrtf(var + BN_EPS) * gamma[tid];
    }
    __syncthreads();
    int t = blockIdx.x * blockDim.x + tid;
    if (t >= n4) return;
    int cb = t & 31;
    float4 a  = ((const float4*)g_agg)[t];
    float4 xr = ((const float4*)x)[t];
    float4 m  = ((const float4*)s_mean)[cb];
    float4 s  = ((const float4*)s_scale)[cb];
    float4 bt = ((const float4*)beta)[cb];
    float4 r;
    r.x = fmaxf((a.x - m.x) * s.x + bt.x, 0.f) + xr.x;
    r.y = fmaxf((a.y - m.y) * s.y + bt.y, 0.f) + xr.y;
    r.z = fmaxf((a.z - m.z) * s.z + bt.z, 0.f) + xr.z;
    r.w = fmaxf((a.w - m.w) * s.w + bt.w, 0.f) + xr.w;
    ((float4*)out)[t] = r;
}

extern "C" void kernel_launch(void* const* d_in, const int* in_sizes, int n_in,
                              void* d_out, int out_size) {
    const float* x     = (const float*)d_in[0];
    const void*  ei    = d_in[1];
    const float* W     = (const float*)d_in[2];
    // d_in[3] = b — cancels exactly through BatchNorm, unused
    const float* gamma = (const float*)d_in[4];
    const float* beta  = (const float*)d_in[5];
    float*       out   = (float*)d_out;

    int N = in_sizes[0] / DD;
    int E = in_sizes[1] / 2;
    int nblk = (N + SCAN_B - 1) / SCAN_B;

    static cudaStream_t s2 = nullptr;
    static cudaEvent_t ev_fork = nullptr, ev_join = nullptr;
    if (s2 == nullptr) {
        cudaStreamCreateWithFlags(&s2, cudaStreamNonBlocking);
        cudaEventCreateWithFlags(&ev_fork, cudaEventDisableTiming);
        cudaEventCreateWithFlags(&ev_join, cudaEventDisableTiming);
    }

    // ---- fork: W-convert + TC GEMM run concurrently with the CSR build ----
    cudaEventRecord(ev_fork, 0);
    cudaStreamWaitEvent(s2, ev_fork, 0);
    k_wcvt<<<(DD * DD + 255) / 256, 256, 0, s2>>>(W);
    int gwarps = (N + 15) / 16;
    k_gemm_tc<<<(gwarps + 7) / 8, 256, 0, s2>>>(x, N);
    cudaEventRecord(ev_join, s2);

    // ---- CSR build chain on the main stream ----
    k_init<<<(N + 255) / 256, 256>>>(ei, N);
    k_prep<<<(E + 255) / 256, 256>>>(ei, E, N);
    k_scan1<<<nblk, SCAN_B>>>(N);
    k_post<<<(N + 255) / 256, 256>>>(N);
    k_fill<<<(E + 255) / 256, 256>>>(ei, E, N);

    // ---- join, then aggregate ----
    cudaStreamWaitEvent(0, ev_join, 0);
    k_gather<<<(N + 7) / 8, 256>>>(N);

    k_bnstats<<<512, 128>>>(N);

    int n4 = N * (DD / 4);
    k_final<<<(n4 + 255) / 256, 256>>>(x, gamma, beta, out, n4, 1.0f / (float)N);
}

// round 11
// speedup vs baseline: 1.6616x; 1.0535x over previous
#include <cuda_runtime.h>
#include <cuda_fp16.h>

#define NN 50000
#define EE 800000
#define DD 128
#define BN_EPS 1e-5f
#define SCAN_B 1024
#define NBLK ((NN + SCAN_B - 1) / SCAN_B)   // 49

// ---- scratch (device globals: zero-initialized at module load) ----
__device__ __align__(16) unsigned g_xwh32[NN * 64];  // x@W as half2 pairs
__device__ unsigned g_wt[DD * DD];            // W pre-converted to tf32 bits
__device__ float    g_agg[NN * DD];
__device__ float    g_dinv[NN];
__device__ int      g_degi[NN];               // ZERO before each prep (see k_gather)
__device__ int      g_off[NN + 1];
__device__ int      g_cur[NN];
__device__ int      g_adj[EE];
__device__ int      g_bsum[NBLK];
__device__ float    g_colsum[DD];             // zeroed in k_post each run
__device__ float    g_colsumsq[DD];

// ---- per-block edge dtype self-detection (first 256 entries as int64) ----
__device__ __forceinline__ int detect_is64(const void* ei, int N, int tid) {
    __shared__ int s_is64;
    long long v = ((const long long*)ei)[tid & 255];
    int bad = (v < 0 || v >= N) ? 1 : 0;
    int any = __syncthreads_or(bad);
    if (tid == 0) s_is64 = !any;
    __syncthreads();
    return s_is64;
}

// ---- K1: histogram rows (self-detecting) ----
__global__ __launch_bounds__(256) void k_prep(const void* __restrict__ ei, int E, int N) {
    int tid = threadIdx.x;
    int is64 = detect_is64(ei, N, tid);
    int e = blockIdx.x * 256 + tid;
    if (e >= E) return;
    int row = is64 ? (int)((const long long*)ei)[e] : ((const int*)ei)[e];
    if ((unsigned)row < (unsigned)N) atomicAdd(&g_degi[row], 1);
}

// ---- K2: per-block inclusive scan + block totals ----
__global__ __launch_bounds__(SCAN_B) void k_scan1(int N) {
    __shared__ int warp_tot[32];
    int tid = threadIdx.x;
    int lane = tid & 31, wid = tid >> 5;
    int i = blockIdx.x * SCAN_B + tid;
    int v = (i < N) ? g_degi[i] : 0;
    int s = v;
#pragma unroll
    for (int d = 1; d < 32; d <<= 1) {
        int t = __shfl_up_sync(0xffffffffu, s, d);
        if (lane >= d) s += t;
    }
    if (lane == 31) warp_tot[wid] = s;
    __syncthreads();
    if (wid == 0) {
        int t = warp_tot[lane];
        int ws = t;
#pragma unroll
        for (int d = 1; d < 32; d <<= 1) {
            int u = __shfl_up_sync(0xffffffffu, ws, d);
            if (lane >= d) ws += u;
        }
        warp_tot[lane] = ws - t;
    }
    __syncthreads();
    int incl = s + warp_tot[wid];
    if (i < N) g_off[i + 1] = incl;
    if (tid == SCAN_B - 1) g_bsum[blockIdx.x] = incl;
}

// ---- K3: finalize offsets + dinv + fill cursors + zero BN accums ----
__global__ void k_post(int N) {
    int i = blockIdx.x * blockDim.x + threadIdx.x;
    if (i < DD) { g_colsum[i] = 0.0f; g_colsumsq[i] = 0.0f; }
    if (i >= N) return;
    int chunk = i >> 10;
    int boff = 0;
    for (int b = 0; b < chunk; b++) boff += g_bsum[b];
    int incl = g_off[i + 1] + boff;
    g_off[i + 1] = incl;
    int deg = g_degi[i];
    g_cur[i] = incl - deg;
    g_dinv[i] = rsqrtf((float)(deg + 1));
    if (i == 0) g_off[0] = 0;
}

// ---- K4: CSR fill over edge range [e0,e1) (self-detecting) ----
__global__ __launch_bounds__(256) void k_fill(const void* __restrict__ ei,
                                              int e0, int e1, int E, int N) {
    int tid = threadIdx.x;
    int is64 = detect_is64(ei, N, tid);
    int e = e0 + blockIdx.x * 256 + tid;
    if (e >= e1) return;
    int row, col;
    if (is64) {
        row = (int)((const long long*)ei)[e];
        col = (int)((const long long*)ei)[E + e];
    } else {
        row = ((const int*)ei)[e];
        col = ((const int*)ei)[E + e];
    }
    if ((unsigned)row >= (unsigned)N || (unsigned)col >= (unsigned)N) return;
    int pos = atomicAdd(&g_cur[row], 1);
    g_adj[pos] = col;
}

// ---- K5a: pre-convert W to tf32 bit pattern ----
__global__ void k_wcvt(const float* __restrict__ W) {
    int i = blockIdx.x * blockDim.x + threadIdx.x;
    if (i < DD * DD) {
        unsigned u;
        asm("cvt.rna.tf32.f32 %0, %1;" : "=r"(u) : "f"(W[i]));
        g_wt[i] = u;
    }
}

// ---- K5b: xw = x @ W via TF32 mma.sync (warp = 16 rows x 128 cols) ----
__global__ __launch_bounds__(256) void k_gemm_tc(const float* __restrict__ x, int N) {
    int lane = threadIdx.x & 31;
    int warp = (blockIdx.x * blockDim.x + threadIdx.x) >> 5;
    int r0 = warp * 16;
    if (r0 >= N) return;
    int gid = lane >> 2;      // 0..7
    int tig = lane & 3;       // 0..3

    float c[16][4];
#pragma unroll
    for (int nt = 0; nt < 16; nt++)
        c[nt][0] = c[nt][1] = c[nt][2] = c[nt][3] = 0.f;

    const float* xr0 = x + (r0 + gid) * DD;
    const float* xr1 = xr0 + 8 * DD;

#pragma unroll
    for (int kt = 0; kt < 16; kt++) {
        int k0 = kt * 8;
        unsigned A0, A1, A2, A3;
        {
            float a0 = xr0[k0 + tig];
            float a1 = xr1[k0 + tig];
            float a2 = xr0[k0 + tig + 4];
            float a3 = xr1[k0 + tig + 4];
            asm("cvt.rna.tf32.f32 %0, %1;" : "=r"(A0) : "f"(a0));
            asm("cvt.rna.tf32.f32 %0, %1;" : "=r"(A1) : "f"(a1));
            asm("cvt.rna.tf32.f32 %0, %1;" : "=r"(A2) : "f"(a2));
            asm("cvt.rna.tf32.f32 %0, %1;" : "=r"(A3) : "f"(a3));
        }
#pragma unroll
        for (int nt = 0; nt < 16; nt++) {
            unsigned B0 = g_wt[(k0 + tig) * DD + nt * 8 + gid];
            unsigned B1 = g_wt[(k0 + tig + 4) * DD + nt * 8 + gid];
            asm volatile(
                "mma.sync.aligned.m16n8k8.row.col.f32.tf32.tf32.f32 "
                "{%0,%1,%2,%3}, {%4,%5,%6,%7}, {%8,%9}, {%0,%1,%2,%3};"
                : "+f"(c[nt][0]), "+f"(c[nt][1]), "+f"(c[nt][2]), "+f"(c[nt][3])
                : "r"(A0), "r"(A1), "r"(A2), "r"(A3), "r"(B0), "r"(B1));
        }
    }

    int row0 = r0 + gid, row1 = r0 + 8 + gid;
#pragma unroll
    for (int nt = 0; nt < 16; nt++) {
        int cH = (nt * 8 + 2 * tig) >> 1;
        __half2 h0 = __float22half2_rn(make_float2(c[nt][0], c[nt][1]));
        __half2 h1 = __float22half2_rn(make_float2(c[nt][2], c[nt][3]));
        g_xwh32[row0 * 64 + cH] = *(unsigned*)&h0;
        g_xwh32[row1 * 64 + cH] = *(unsigned*)&h1;
    }
}

// ---- K6: per-node gather (unroll-4) + re-zero degi for next run ----
__global__ __launch_bounds__(256) void k_gather(int N) {
    int gt = blockIdx.x * blockDim.x + threadIdx.x;
    if (gt < N) g_degi[gt] = 0;            // degi dead after k_post; reset for next replay
    int lane = threadIdx.x & 31;
    int n = gt >> 5;
    if (n >= N) return;
    int j = g_off[n], end = g_off[n + 1];
    const uint2* xwh = (const uint2*)g_xwh32;

    float4 acc = make_float4(0.f, 0.f, 0.f, 0.f);
    for (; j + 4 <= end; j += 4) {
        int c0 = g_adj[j], c1 = g_adj[j + 1], c2 = g_adj[j + 2], c3 = g_adj[j + 3];
        float w0 = g_dinv[c0], w1 = g_dinv[c1], w2 = g_dinv[c2], w3 = g_dinv[c3];
        uint2 u0 = xwh[c0 * 32 + lane];
        uint2 u1 = xwh[c1 * 32 + lane];
        uint2 u2 = xwh[c2 * 32 + lane];
        uint2 u3 = xwh[c3 * 32 + lane];
        float2 a0 = __half22float2(*(__half2*)&u0.x), b0 = __half22float2(*(__half2*)&u0.y);
        float2 a1 = __half22float2(*(__half2*)&u1.x), b1 = __half22float2(*(__half2*)&u1.y);
        float2 a2 = __half22float2(*(__half2*)&u2.x), b2 = __half22float2(*(__half2*)&u2.y);
        float2 a3 = __half22float2(*(__half2*)&u3.x), b3 = __half22float2(*(__half2*)&u3.y);
        acc.x = fmaf(a0.x, w0, fmaf(a1.x, w1, fmaf(a2.x, w2, fmaf(a3.x, w3, acc.x))));
        acc.y = fmaf(a0.y, w0, fmaf(a1.y, w1, fmaf(a2.y, w2, fmaf(a3.y, w3, acc.y))));
        acc.z = fmaf(b0.x, w0, fmaf(b1.x, w1, fmaf(b2.x, w2, fmaf(b3.x, w3, acc.z))));
        acc.w = fmaf(b0.y, w0, fmaf(b1.y, w1, fmaf(b2.y, w2, fmaf(b3.y, w3, acc.w))));
    }
    for (; j < end; j++) {
        int c0 = g_adj[j];
        float w0 = g_dinv[c0];
        uint2 u0 = xwh[c0 * 32 + lane];
        float2 a0 = __half22float2(*(__half2*)&u0.x), b0 = __half22float2(*(__half2*)&u0.y);
        acc.x = fmaf(a0.x, w0, acc.x);
        acc.y = fmaf(a0.y, w0, acc.y);
        acc.z = fmaf(b0.x, w0, acc.z);
        acc.w = fmaf(b0.y, w0, acc.w);
    }
    float dr = g_dinv[n];
    uint2 us = xwh[n * 32 + lane];
    float2 sa = __half22float2(*(__half2*)&us.x), sb = __half22float2(*(__half2*)&us.y);
    acc.x = (acc.x + sa.x * dr) * dr;
    acc.y = (acc.y + sa.y * dr) * dr;
    acc.z = (acc.z + sb.x * dr) * dr;
    acc.w = (acc.w + sb.y * dr) * dr;
    ((float4*)g_agg)[n * 32 + lane] = acc;
}

// ---- K7: BN column statistics ----
__global__ void k_bnstats(int N) {
    int c = threadIdx.x;
    float s = 0.f, s2 = 0.f;
    for (int r = blockIdx.x; r < N; r += gridDim.x) {
        float v = g_agg[r * DD + c];
        s += v;
        s2 = fmaf(v, v, s2);
    }
    atomicAdd(&g_colsum[c], s);
    atomicAdd(&g_colsumsq[c], s2);
}

// ---- K8: y = relu((agg-mean)*scale + beta) + x, BN params per-block ----
__global__ __launch_bounds__(256) void k_final(const float* __restrict__ x,
                                               const float* __restrict__ gamma,
                                               const float* __restrict__ beta,
                                               float* __restrict__ out,
                                               int n4, float nInv) {
    __shared__ float s_mean[DD], s_scale[DD];
    int tid = threadIdx.x;
    if (tid < DD) {
        float mean = g_colsum[tid] * nInv;
        float var = g_colsumsq[tid] * nInv - mean * mean;
        s_mean[tid] = mean;
        s_scale[tid] = rsqrtf(var + BN_EPS) * gamma[tid];
    }
    __syncthreads();
    int t = blockIdx.x * blockDim.x + tid;
    if (t >= n4) return;
    int cb = t & 31;
    float4 a  = ((const float4*)g_agg)[t];
    float4 xr = ((const float4*)x)[t];
    float4 m  = ((const float4*)s_mean)[cb];
    float4 s  = ((const float4*)s_scale)[cb];
    float4 bt = ((const float4*)beta)[cb];
    float4 r;
    r.x = fmaxf((a.x - m.x) * s.x + bt.x, 0.f) + xr.x;
    r.y = fmaxf((a.y - m.y) * s.y + bt.y, 0.f) + xr.y;
    r.z = fmaxf((a.z - m.z) * s.z + bt.z, 0.f) + xr.z;
    r.w = fmaxf((a.w - m.w) * s.w + bt.w, 0.f) + xr.w;
    ((float4*)out)[t] = r;
}

extern "C" void kernel_launch(void* const* d_in, const int* in_sizes, int n_in,
                              void* d_out, int out_size) {
    const float* x     = (const float*)d_in[0];
    const void*  ei    = d_in[1];
    const float* W     = (const float*)d_in[2];
    // d_in[3] = b — cancels exactly through BatchNorm, unused
    const float* gamma = (const float*)d_in[4];
    const float* beta  = (const float*)d_in[5];
    float*       out   = (float*)d_out;

    int N = in_sizes[0] / DD;
    int E = in_sizes[1] / 2;
    int nblk = (N + SCAN_B - 1) / SCAN_B;
    int Eh = E / 2;

    static cudaStream_t s2 = nullptr;
    static cudaEvent_t ev_fork = nullptr, ev_post = nullptr, ev_join = nullptr;
    if (s2 == nullptr) {
        cudaStreamCreateWithFlags(&s2, cudaStreamNonBlocking);
        cudaEventCreateWithFlags(&ev_fork, cudaEventDisableTiming);
        cudaEventCreateWithFlags(&ev_post, cudaEventDisableTiming);
        cudaEventCreateWithFlags(&ev_join, cudaEventDisableTiming);
    }

    // ---- fork: s2 runs W-convert + TC GEMM, then helps fill ----
    cudaEventRecord(ev_fork, 0);
    cudaStreamWaitEvent(s2, ev_fork, 0);
    k_wcvt<<<(DD * DD + 255) / 256, 256, 0, s2>>>(W);
    int gwarps = (N + 15) / 16;
    k_gemm_tc<<<(gwarps + 7) / 8, 256, 0, s2>>>(x, N);

    // ---- main: CSR build ----
    k_prep<<<(E + 255) / 256, 256>>>(ei, E, N);
    k_scan1<<<nblk, SCAN_B>>>(N);
    k_post<<<(N + 255) / 256, 256>>>(N);
    cudaEventRecord(ev_post, 0);

    // fill split: main does [0,Eh), s2 does [Eh,E) after post
    cudaStreamWaitEvent(s2, ev_post, 0);
    k_fill<<<(E - Eh + 255) / 256, 256, 0, s2>>>(ei, Eh, E, E, N);
    cudaEventRecord(ev_join, s2);
    k_fill<<<(Eh + 255) / 256, 256>>>(ei, 0, Eh, E, N);

    // ---- join, then aggregate ----
    cudaStreamWaitEvent(0, ev_join, 0);
    k_gather<<<(N + 7) / 8, 256>>>(N);

    k_bnstats<<<512, 128>>>(N);

    int n4 = N * (DD / 4);
    k_final<<<(n4 + 255) / 256, 256>>>(x, gamma, beta, out, n4, 1.0f / (float)N);
}